// round 10
// baseline (speedup 1.0000x reference)
#include <cuda_runtime.h>
#include <cuda_bf16.h>
#include <math.h>

// Scratch (no allocations allowed): per-block partials + completion counter.
// Every g_part slot used in a launch is rewritten that launch; g_count
// self-resets to 0 in the last block -> deterministic across graph replays.
#define MAX_BLOCKS 4096
__device__ float g_part[MAX_BLOCKS];
__device__ unsigned int g_count = 0;

#define TPB 256
#define EPW 512                 // elements per warp (contiguous 16KB span)
#define NITER (EPW / 16)        // 32: one LDG.128/lane covers 16 elements/warp
#define EPB (EPW * (TPB / 32))  // 4096 elements per block

__global__ void __launch_bounds__(TPB, 4) nll_wide_kernel(
    const float* __restrict__ pred,          // (n, 8) fp32, channel 0 used
    const unsigned char* __restrict__ mask,  // (n,) bool (1 byte)
    float* __restrict__ out)
{
    const int lane = threadIdx.x & 31;
    const int warp = threadIdx.x >> 5;
    const int gw = blockIdx.x * (TPB / 32) + warp;   // global warp id

    // Warp gw owns elements [gw*EPW, gw*EPW + EPW).
    // Per iteration the warp loads 512 CONTIGUOUS bytes (32 lanes x float4):
    // full 128B-line requests -> 4-sector L2 miss transactions instead of the
    // 1-sector transactions a stride-32B LDG.32 pattern produces. Only even
    // lanes' .x is a channel-0 value (odd lanes carry channels 4-7, unused);
    // traffic is identical either way -- the whole array must stream.
    const float4* __restrict__ p4 = (const float4*)pred;
    const size_t base = (size_t)gw * EPW;
    const bool active = (lane & 1) == 0;
    const int j = lane >> 1;                 // element-within-16 for even lanes

    float s = 0.0f;

    #pragma unroll
    for (int kk = 0; kk < NITER; kk += 8) {
        float4 v[8];
        unsigned char m[8];
        #pragma unroll
        for (int u = 0; u < 8; u++) {
            size_t e0 = base + (size_t)(kk + u) * 16;
            v[u] = __ldcs(&p4[e0 * 2 + lane]);       // contiguous across warp
        }
        #pragma unroll
        for (int u = 0; u < 8; u++) {
            size_t e0 = base + (size_t)(kk + u) * 16;
            m[u] = __ldcs(&mask[e0 + j]);            // 16B/warp, 1 sector
        }
        #pragma unroll
        for (int u = 0; u < 8; u++) {
            if (active) {
                // log(p) if masked else log(1-p). 1-p exact for p>=0.5
                // (Sterbenz), <=0.5ulp otherwise -> noise-level error in a
                // 4M-term sum at 1e-3 tolerance.
                float p = v[u].x;
                s += logf(m[u] ? p : 1.0f - p);
            }
        }
    }

    // Warp reduction.
    #pragma unroll
    for (int o = 16; o > 0; o >>= 1)
        s += __shfl_xor_sync(0xFFFFFFFFu, s, o);

    __shared__ float warp_sums[TPB / 32];
    if (lane == 0) warp_sums[warp] = s;
    __syncthreads();

    if (warp == 0) {
        float bs = (lane < (TPB >> 5)) ? warp_sums[lane] : 0.0f;
        #pragma unroll
        for (int o = 4; o > 0; o >>= 1)
            bs += __shfl_xor_sync(0xFFFFFFFFu, bs, o);
        if (lane == 0) g_part[blockIdx.x] = bs;
    }

    // Elect the last block to finish (threadfence-reduction pattern).
    __shared__ bool is_last;
    __threadfence();
    if (threadIdx.x == 0) {
        unsigned int c = atomicAdd(&g_count, 1u);
        is_last = (c == gridDim.x - 1);
    }
    __syncthreads();

    if (is_last) {
        double d = 0.0;
        for (int i = threadIdx.x; i < (int)gridDim.x; i += TPB)
            d += (double)g_part[i];

        #pragma unroll
        for (int o = 16; o > 0; o >>= 1)
            d += __shfl_xor_sync(0xFFFFFFFFu, d, o);

        __shared__ double dwarp[TPB / 32];
        if (lane == 0) dwarp[warp] = d;
        __syncthreads();
        if (warp == 0) {
            double bd = (lane < (TPB >> 5)) ? dwarp[lane] : 0.0;
            #pragma unroll
            for (int o = 4; o > 0; o >>= 1)
                bd += __shfl_xor_sync(0xFFFFFFFFu, bd, o);
            if (lane == 0) {
                out[0] = (float)(-bd * (1.0 / 256.0));
                g_count = 0;  // self-reset for next graph replay
            }
        }
    }
}

// Generic fallback for shapes not divisible by EPB.
__global__ void __launch_bounds__(TPB) nll_fallback_kernel(
    const float* __restrict__ pred,
    const unsigned char* __restrict__ mask,
    float* __restrict__ out, int n)
{
    const int tid = blockIdx.x * TPB + threadIdx.x;
    const int stride = gridDim.x * TPB;
    float s = 0.0f;
    #pragma unroll 4
    for (int i = tid; i < n; i += stride) {
        float p = __ldg(&pred[(size_t)i * 8]);
        s += mask[i] ? logf(p) : log1pf(-p);
    }

    #pragma unroll
    for (int o = 16; o > 0; o >>= 1)
        s += __shfl_xor_sync(0xFFFFFFFFu, s, o);

    __shared__ float warp_sums[TPB / 32];
    const int lane = threadIdx.x & 31;
    const int warp = threadIdx.x >> 5;
    if (lane == 0) warp_sums[warp] = s;
    __syncthreads();

    if (warp == 0) {
        float bs = (lane < (TPB >> 5)) ? warp_sums[lane] : 0.0f;
        #pragma unroll
        for (int o = 4; o > 0; o >>= 1)
            bs += __shfl_xor_sync(0xFFFFFFFFu, bs, o);
        if (lane == 0) g_part[blockIdx.x] = bs;
    }

    __shared__ bool is_last;
    __threadfence();
    if (threadIdx.x == 0) {
        unsigned int c = atomicAdd(&g_count, 1u);
        is_last = (c == gridDim.x - 1);
    }
    __syncthreads();

    if (is_last) {
        double d = 0.0;
        for (int i = threadIdx.x; i < (int)gridDim.x; i += TPB)
            d += (double)g_part[i];
        #pragma unroll
        for (int o = 16; o > 0; o >>= 1)
            d += __shfl_xor_sync(0xFFFFFFFFu, d, o);
        __shared__ double dwarp[TPB / 32];
        if (lane == 0) dwarp[warp] = d;
        __syncthreads();
        if (warp == 0) {
            double bd = (lane < (TPB >> 5)) ? dwarp[lane] : 0.0;
            #pragma unroll
            for (int o = 4; o > 0; o >>= 1)
                bd += __shfl_xor_sync(0xFFFFFFFFu, bd, o);
            if (lane == 0) {
                out[0] = (float)(-bd * (1.0 / 256.0));
                g_count = 0;
            }
        }
    }
}

extern "C" void kernel_launch(void* const* d_in, const int* in_sizes, int n_in,
                              void* d_out, int out_size)
{
    const float* pred = (const float*)d_in[0];
    const unsigned char* mask = (const unsigned char*)d_in[1];
    float* out = (float*)d_out;

    int n = in_sizes[1];                       // 4,194,304 expected

    if (n > 0 && (n % EPB) == 0 && (n / EPB) <= MAX_BLOCKS) {
        int blocks = n / EPB;                  // 1024 for n=4M
        nll_wide_kernel<<<blocks, TPB>>>(pred, mask, out);
    } else {
        int blocks = (n + TPB * 8 - 1) / (TPB * 8);
        if (blocks < 1) blocks = 1;
        if (blocks > MAX_BLOCKS) blocks = MAX_BLOCKS;
        nll_fallback_kernel<<<blocks, TPB>>>(pred, mask, out, n);
    }
}

// round 11
// speedup vs baseline: 1.0667x; 1.0667x over previous
#include <cuda_runtime.h>
#include <cuda_bf16.h>
#include <math.h>

// Scratch (no allocations allowed). 32 spread double bins (atomics to
// distinct addresses overlap with other CTAs' work; per-address serialization
// is only gridDim/32 deep) + completion counter. Last block resets both ->
// deterministic across graph replays (bins are zero-init at module load).
#define NBINS 32
__device__ double g_bins[NBINS];
__device__ unsigned int g_count = 0;

#define TPB 256
#define ILP 8

__global__ void __launch_bounds__(TPB) nll_fused_kernel(
    const float* __restrict__ pred,          // (n, 8) fp32, channel 0 used
    const unsigned char* __restrict__ mask,  // (n,) bool (1 byte)
    float* __restrict__ out,
    int n)
{
    const int tid = blockIdx.x * TPB + threadIdx.x;
    const int stride = gridDim.x * TPB;

    float s = 0.0f;

    if (n == stride * ILP) {
        // Best-measured load schedule (R8): ILP 8, fully front-batched
        // (16 independent LDGs before any consumer), evict-first streaming.
        // Lanes hit consecutive 32B sectors (row stride = 8 floats).
        float p[ILP];
        unsigned int mword[ILP];
        #pragma unroll
        for (int k = 0; k < ILP; k++) {
            int e = tid + k * stride;
            asm volatile("ld.global.cs.f32 %0, [%1];"
                         : "=f"(p[k]) : "l"(&pred[(size_t)e * 8]));
        }
        #pragma unroll
        for (int k = 0; k < ILP; k++) {
            int e = tid + k * stride;
            asm volatile("ld.global.cs.u8 %0, [%1];"
                         : "=r"(mword[k]) : "l"(&mask[e]));
        }
        #pragma unroll
        for (int k = 0; k < ILP; k++) {
            // log(p) if masked else log(1-p). 1-p is exact for p>=0.5
            // (Sterbenz) and <=0.5ulp otherwise: per-element error ~2e-7,
            // random sign -> invisible in the 4M-term sum at 1e-3 tol.
            float q = mword[k] ? p[k] : 1.0f - p[k];
            s += logf(q);
        }
    } else {
        // Generic fallback (any n).
        #pragma unroll 4
        for (int i = tid; i < n; i += stride) {
            float p = __ldg(&pred[(size_t)i * 8]);
            s += mask[i] ? logf(p) : log1pf(-p);
        }
    }

    // Warp reduction.
    #pragma unroll
    for (int o = 16; o > 0; o >>= 1)
        s += __shfl_xor_sync(0xFFFFFFFFu, s, o);

    __shared__ float warp_sums[TPB / 32];
    const int lane = threadIdx.x & 31;
    const int warp = threadIdx.x >> 5;
    if (lane == 0) warp_sums[warp] = s;
    __syncthreads();

    // Thread 0: block sum -> spread double bin (overlapped with other CTAs'
    // streaming), then elect the last block via counter.
    if (threadIdx.x == 0) {
        float bs = 0.0f;
        #pragma unroll
        for (int w = 0; w < TPB / 32; w++) bs += warp_sums[w];

        atomicAdd(&g_bins[blockIdx.x & (NBINS - 1)], (double)bs);
        __threadfence();
        unsigned int c = atomicAdd(&g_count, 1u);
        if (c == gridDim.x - 1) {
            // Tiny tail: read 32 doubles, sum, emit, reset.
            double tot = 0.0;
            #pragma unroll
            for (int b = 0; b < NBINS; b++) {
                tot += g_bins[b];
                g_bins[b] = 0.0;           // reset for next graph replay
            }
            out[0] = (float)(-tot * (1.0 / 256.0));
            g_count = 0;
        }
    }
}

extern "C" void kernel_launch(void* const* d_in, const int* in_sizes, int n_in,
                              void* d_out, int out_size)
{
    const float* pred = (const float*)d_in[0];
    const unsigned char* mask = (const unsigned char*)d_in[1];
    float* out = (float*)d_out;

    int n = in_sizes[1];                             // 4,194,304 expected

    int blocks = (n + TPB * ILP - 1) / (TPB * ILP);  // 2048 for n=4M
    if (blocks < 1) blocks = 1;
    if (blocks > 65535) blocks = 65535;              // fallback path handles rest

    nll_fused_kernel<<<blocks, TPB>>>(pred, mask, out, n);
}